// round 1
// baseline (speedup 1.0000x reference)
#include <cuda_runtime.h>
#include <math.h>

#define SEQ    256
#define BATCH  64
#define EMBED  512
#define HIDDEN 512
#define VOCAB  10000
#define ROWS   (SEQ*BATCH)      /* 16384 */
#define G4     (4*HIDDEN)       /* 2048  */

// ---------------- scratch (static device globals; no runtime allocation) ----
__device__ float g_xproj[(size_t)ROWS * G4];        // [row][2048], bias folded in
__device__ float g_hs[(size_t)ROWS * HIDDEN];       // [s][b][512]
__device__ float g_h[BATCH * HIDDEN];
__device__ float g_c[BATCH * HIDDEN];
__device__ float g_part[128 * BATCH * 128];         // [blk(jt,ks)][b][128]
__device__ int   g_cnt[16];

__device__ __forceinline__ float sigf(float x)  { return 1.0f / (1.0f + __expf(-x)); }
__device__ __forceinline__ float tanhx(float x) { return 2.0f / (1.0f + __expf(-2.0f * x)) - 1.0f; }

// ---------------- init: zero h, c, counters --------------------------------
__global__ void k_init() {
    int i = blockIdx.x * blockDim.x + threadIdx.x;
    if (i < BATCH * HIDDEN) { g_h[i] = 0.0f; g_c[i] = 0.0f; }
    if (i < 16) g_cnt[i] = 0;
}

// ---------------- kernel A: embed gather + x-projection GEMM ---------------
// out[row][gate*512 + jj] = sum_k emb[idx[row]][k] * wxG[k][jj] + bG[jj]
// grid: (16 col tiles of 128, 128 row tiles of 128), 256 threads, 8x8 micro.
__global__ __launch_bounds__(256) void k_xproj(
    const int* __restrict__ idx, const float* __restrict__ emb,
    const float* __restrict__ wx0, const float* __restrict__ wx1,
    const float* __restrict__ wx2, const float* __restrict__ wx3,
    const float* __restrict__ bb0, const float* __restrict__ bb1,
    const float* __restrict__ bb2, const float* __restrict__ bb3)
{
    __shared__ float As[16][128];
    __shared__ float Bs[16][128];
    __shared__ int   idx_s[128];
    const int tid = threadIdx.x;
    const int bx = blockIdx.x;           // 0..15
    const int by = blockIdx.y;           // 0..127
    const int gate = bx >> 2;
    const int jj0  = (bx & 3) * 128;
    const float* wB = (gate == 0) ? wx0 : (gate == 1) ? wx1 : (gate == 2) ? wx2 : wx3;
    const float* bB = (gate == 0) ? bb0 : (gate == 1) ? bb1 : (gate == 2) ? bb2 : bb3;

    if (tid < 128) idx_s[tid] = idx[by * 128 + tid];
    __syncthreads();

    const int ty = tid >> 4, tx = tid & 15;
    float acc[8][8] = {};

    const int am  = tid >> 2;
    const int akv = (tid & 3) * 4;
    const int br  = tid >> 5;
    const int bcv = (tid & 31) * 4;

    for (int k0 = 0; k0 < EMBED; k0 += 16) {
        #pragma unroll
        for (int i = 0; i < 2; i++) {
            int m = am + 64 * i;
            float4 v = *(const float4*)(emb + (size_t)idx_s[m] * EMBED + k0 + akv);
            As[akv + 0][m] = v.x; As[akv + 1][m] = v.y;
            As[akv + 2][m] = v.z; As[akv + 3][m] = v.w;
        }
        #pragma unroll
        for (int i = 0; i < 2; i++) {
            int r = br + 8 * i;
            *(float4*)&Bs[r][bcv] =
                *(const float4*)(wB + (size_t)(k0 + r) * HIDDEN + jj0 + bcv);
        }
        __syncthreads();
        #pragma unroll
        for (int kk = 0; kk < 16; kk++) {
            float a[8], b[8];
            *(float4*)&a[0] = *(const float4*)&As[kk][ty * 8];
            *(float4*)&a[4] = *(const float4*)&As[kk][ty * 8 + 4];
            *(float4*)&b[0] = *(const float4*)&Bs[kk][tx * 8];
            *(float4*)&b[4] = *(const float4*)&Bs[kk][tx * 8 + 4];
            #pragma unroll
            for (int i = 0; i < 8; i++)
                #pragma unroll
                for (int j = 0; j < 8; j++)
                    acc[i][j] = fmaf(a[i], b[j], acc[i][j]);
        }
        __syncthreads();
    }

    float bv[8];
    #pragma unroll
    for (int j = 0; j < 8; j++) bv[j] = bB[jj0 + tx * 8 + j];
    #pragma unroll
    for (int i = 0; i < 8; i++) {
        size_t row = (size_t)by * 128 + ty * 8 + i;
        float* o = g_xproj + row * G4 + gate * HIDDEN + jj0 + tx * 8;
        #pragma unroll
        for (int j = 0; j < 8; j++) o[j] = acc[i][j] + bv[j];
    }
}

// ---------------- per-step recurrence kernel -------------------------------
// grid 128: jt = blk>>3 (16 tiles of 32 hidden cols x 4 gates), ks = blk&7
// (8-way split of K=512). GEMM partials -> g_part; last CTA per jt reduces,
// applies gate nonlinearity, writes h/c/hs.
__global__ __launch_bounds__(256) void k_step(
    const float* __restrict__ wh0, const float* __restrict__ wh1,
    const float* __restrict__ wh2, const float* __restrict__ wh3,
    const int s)
{
    __shared__ float As[64][64];     // [k][b]
    __shared__ float Bs[64][128];    // [k][4*32 cols]
    const int tid = threadIdx.x;
    const int bx  = blockIdx.x;
    const int jt  = bx >> 3;
    const int ks  = bx & 7;

    {   // load h chunk [64 b][64 k] transposed
        const int b = tid >> 2, q = tid & 3;
        #pragma unroll
        for (int i = 0; i < 4; i++) {
            int kf = q + 4 * i;
            float4 v = *(const float4*)(g_h + b * HIDDEN + ks * 64 + kf * 4);
            As[kf * 4 + 0][b] = v.x; As[kf * 4 + 1][b] = v.y;
            As[kf * 4 + 2][b] = v.z; As[kf * 4 + 3][b] = v.w;
        }
    }
    {   // load wh tile: cols = gate*32 + e
        const int cv = tid & 31;
        const int gate = cv >> 3;
        const float* w = (gate == 0) ? wh0 : (gate == 1) ? wh1 : (gate == 2) ? wh2 : wh3;
        const int jc = jt * 32 + (cv & 7) * 4;
        #pragma unroll
        for (int i = 0; i < 8; i++) {
            int r = (tid >> 5) + 8 * i;
            *(float4*)&Bs[r][cv * 4] =
                *(const float4*)(w + (size_t)(ks * 64 + r) * HIDDEN + jc);
        }
    }
    __syncthreads();

    const int ty = tid >> 5, tx = tid & 31;   // 8x4 micro-tile
    float acc[8][4] = {};
    #pragma unroll 8
    for (int kk = 0; kk < 64; kk++) {
        float a[8], b[4];
        *(float4*)&a[0] = *(const float4*)&As[kk][ty * 8];
        *(float4*)&a[4] = *(const float4*)&As[kk][ty * 8 + 4];
        *(float4*)&b[0] = *(const float4*)&Bs[kk][tx * 4];
        #pragma unroll
        for (int i = 0; i < 8; i++)
            #pragma unroll
            for (int j = 0; j < 4; j++)
                acc[i][j] = fmaf(a[i], b[j], acc[i][j]);
    }

    float* p = g_part + (size_t)bx * (BATCH * 128);
    #pragma unroll
    for (int i = 0; i < 8; i++) {
        float4 v = make_float4(acc[i][0], acc[i][1], acc[i][2], acc[i][3]);
        *(float4*)&p[(ty * 8 + i) * 128 + tx * 4] = v;
    }
    __threadfence();
    __syncthreads();

    __shared__ int elect;
    if (tid == 0) {
        int old = atomicAdd(&g_cnt[jt], 1);
        elect = (old == 7);
    }
    __syncthreads();
    if (!elect) return;
    __threadfence();
    if (tid == 0) g_cnt[jt] = 0;   // reset for next step's launch

    // reduce partials + gate math for tile jt: elems (b in 64, e in 32)
    #pragma unroll
    for (int g2 = 0; g2 < 2; g2++) {
        int grp = tid + 256 * g2;          // 0..511
        int b   = grp >> 3;                // 0..63
        int e4  = (grp & 7) * 4;           // 0..28 step 4
        const float* xp = g_xproj + (size_t)(s * BATCH + b) * G4 + jt * 32 + e4;
        float4 gi = *(const float4*)(xp + 0 * HIDDEN);
        float4 gf = *(const float4*)(xp + 1 * HIDDEN);
        float4 gc = *(const float4*)(xp + 2 * HIDDEN);
        float4 go = *(const float4*)(xp + 3 * HIDDEN);
        #pragma unroll
        for (int kq = 0; kq < 8; kq++) {
            const float* pp = g_part + (size_t)(jt * 8 + kq) * (BATCH * 128) + b * 128;
            float4 v;
            v = __ldcg((const float4*)(pp + 0 * 32 + e4)); gi.x += v.x; gi.y += v.y; gi.z += v.z; gi.w += v.w;
            v = __ldcg((const float4*)(pp + 1 * 32 + e4)); gf.x += v.x; gf.y += v.y; gf.z += v.z; gf.w += v.w;
            v = __ldcg((const float4*)(pp + 2 * 32 + e4)); gc.x += v.x; gc.y += v.y; gc.z += v.z; gc.w += v.w;
            v = __ldcg((const float4*)(pp + 3 * 32 + e4)); go.x += v.x; go.y += v.y; go.z += v.z; go.w += v.w;
        }
        int ci = b * HIDDEN + jt * 32 + e4;
        float4 cold = *(const float4*)(g_c + ci);
        float4 cnew, hh;
        cnew.x = sigf(gf.x) * cold.x + sigf(gi.x) * tanhx(gc.x);
        cnew.y = sigf(gf.y) * cold.y + sigf(gi.y) * tanhx(gc.y);
        cnew.z = sigf(gf.z) * cold.z + sigf(gi.z) * tanhx(gc.z);
        cnew.w = sigf(gf.w) * cold.w + sigf(gi.w) * tanhx(gc.w);
        hh.x = sigf(go.x) * tanhx(cnew.x);
        hh.y = sigf(go.y) * tanhx(cnew.y);
        hh.z = sigf(go.z) * tanhx(cnew.z);
        hh.w = sigf(go.w) * tanhx(cnew.w);
        *(float4*)(g_c + ci) = cnew;
        *(float4*)(g_h + ci) = hh;
        *(float4*)(g_hs + (size_t)s * (BATCH * HIDDEN) + ci) = hh;
    }
}

// ---------------- kernel C: output projection GEMM -------------------------
// out[row][v] = sum_k hs[row][k] * wy[k][v] + by[v];  N = 10000 (bounds).
__global__ __launch_bounds__(256) void k_out(
    const float* __restrict__ wy, const float* __restrict__ byv,
    float* __restrict__ out)
{
    __shared__ float As[16][128];
    __shared__ float Bs[16][128];
    const int tid = threadIdx.x;
    const int bx = blockIdx.x;   // 0..78
    const int by = blockIdx.y;   // 0..127
    const int n0 = bx * 128;
    const int ty = tid >> 4, tx = tid & 15;
    float acc[8][8] = {};

    const int am  = tid >> 2;
    const int akv = (tid & 3) * 4;
    const int br  = tid >> 5;
    const int bcv = (tid & 31) * 4;

    for (int k0 = 0; k0 < HIDDEN; k0 += 16) {
        #pragma unroll
        for (int i = 0; i < 2; i++) {
            int m = am + 64 * i;
            float4 v = *(const float4*)(g_hs + (size_t)(by * 128 + m) * HIDDEN + k0 + akv);
            As[akv + 0][m] = v.x; As[akv + 1][m] = v.y;
            As[akv + 2][m] = v.z; As[akv + 3][m] = v.w;
        }
        #pragma unroll
        for (int i = 0; i < 2; i++) {
            int r = br + 8 * i;
            int col = n0 + bcv;
            float4 v = make_float4(0.f, 0.f, 0.f, 0.f);
            if (col < VOCAB)
                v = *(const float4*)(wy + (size_t)(k0 + r) * VOCAB + col);
            *(float4*)&Bs[r][bcv] = v;
        }
        __syncthreads();
        #pragma unroll
        for (int kk = 0; kk < 16; kk++) {
            float a[8], b[8];
            *(float4*)&a[0] = *(const float4*)&As[kk][ty * 8];
            *(float4*)&a[4] = *(const float4*)&As[kk][ty * 8 + 4];
            *(float4*)&b[0] = *(const float4*)&Bs[kk][tx * 8];
            *(float4*)&b[4] = *(const float4*)&Bs[kk][tx * 8 + 4];
            #pragma unroll
            for (int i = 0; i < 8; i++)
                #pragma unroll
                for (int j = 0; j < 8; j++)
                    acc[i][j] = fmaf(a[i], b[j], acc[i][j]);
        }
        __syncthreads();
    }

    int colb = n0 + tx * 8;
    if (colb + 8 <= VOCAB) {   // VOCAB % 8 == 0: groups are all-or-nothing
        float bv[8];
        #pragma unroll
        for (int j = 0; j < 8; j++) bv[j] = byv[colb + j];
        #pragma unroll
        for (int i = 0; i < 8; i++) {
            size_t row = (size_t)by * 128 + ty * 8 + i;
            float* o = out + row * VOCAB + colb;
            #pragma unroll
            for (int j = 0; j < 8; j++) o[j] = acc[i][j] + bv[j];
        }
    }
}

// ---------------- tail: ht, ct ---------------------------------------------
__global__ void k_tail(float* out) {
    int i = blockIdx.x * blockDim.x + threadIdx.x;
    size_t base = (size_t)ROWS * VOCAB;
    if (i < BATCH * HIDDEN)
        out[base + i] = g_hs[(size_t)(SEQ - 1) * (BATCH * HIDDEN) + i];
    else if (i < 2 * BATCH * HIDDEN)
        out[base + i] = g_c[i - BATCH * HIDDEN];
}

// ---------------- launch ----------------------------------------------------
extern "C" void kernel_launch(void* const* d_in, const int* in_sizes, int n_in,
                              void* d_out, int out_size) {
    const int*   input_ = (const int*)  d_in[0];
    const float* emb    = (const float*)d_in[1];
    const float* wxi    = (const float*)d_in[2];
    const float* whi    = (const float*)d_in[3];
    const float* bi     = (const float*)d_in[4];
    const float* wxf    = (const float*)d_in[5];
    const float* whf    = (const float*)d_in[6];
    const float* bf     = (const float*)d_in[7];
    const float* wxc    = (const float*)d_in[8];
    const float* whc    = (const float*)d_in[9];
    const float* bc     = (const float*)d_in[10];
    const float* wxo    = (const float*)d_in[11];
    const float* who    = (const float*)d_in[12];
    const float* bo     = (const float*)d_in[13];
    const float* wy     = (const float*)d_in[14];
    const float* by     = (const float*)d_in[15];
    float* out = (float*)d_out;

    k_init<<<128, 256>>>();

    dim3 gA(16, 128);
    k_xproj<<<gA, 256>>>(input_, emb, wxi, wxf, wxc, wxo, bi, bf, bc, bo);

    for (int s = 0; s < SEQ; s++)
        k_step<<<128, 256>>>(whi, whf, whc, who, s);

    dim3 gC(79, 128);
    k_out<<<gC, 256>>>(wy, by, out);

    if ((long long)out_size >= (long long)ROWS * VOCAB + 2LL * BATCH * HIDDEN)
        k_tail<<<(2 * BATCH * HIDDEN + 255) / 256, 256>>>(out);
}

// round 2
// speedup vs baseline: 1.0997x; 1.0997x over previous
#include <cuda_runtime.h>
#include <math.h>

#define SEQ    256
#define BATCH  64
#define EMBED  512
#define HIDDEN 512
#define VOCAB  10000
#define ROWS   (SEQ*BATCH)      /* 16384 */
#define G4     (4*HIDDEN)       /* 2048  */
#define NCTA   128
#define NTHR   256
#define HSLOT  (HIDDEN*BATCH)   /* 32768 floats per h slot */

typedef unsigned long long ull;

// ---------------- scratch (static device globals) ---------------------------
__device__ float g_xproj[(size_t)ROWS * G4];              // [row][2048], bias folded
__device__ __align__(16) float g_hs_buf[(size_t)(SEQ + 1) * HSLOT];  // [s][k][b] transposed
__device__ float g_c[BATCH * HIDDEN];
__device__ unsigned g_arrive;
__device__ volatile unsigned g_epoch;

__device__ __forceinline__ float sigf(float x)  { return 1.0f / (1.0f + __expf(-x)); }
__device__ __forceinline__ float tanhx(float x) { return 2.0f / (1.0f + __expf(-2.0f * x)) - 1.0f; }

__device__ __forceinline__ ull pk2(float x) {
    ull r; asm("mov.b64 %0, {%1, %2};" : "=l"(r) : "f"(x), "f"(x)); return r;
}
__device__ __forceinline__ void unpk(ull v, float& lo, float& hi) {
    asm("mov.b64 {%0, %1}, %2;" : "=f"(lo), "=f"(hi) : "l"(v));
}
__device__ __forceinline__ void fma2(ull& d, ull a, ull b) {
    asm("fma.rn.f32x2 %0, %1, %2, %0;" : "+l"(d) : "l"(a), "l"(b));
}
__device__ __forceinline__ void cp_async16(void* dst, const void* src) {
    unsigned a = (unsigned)__cvta_generic_to_shared(dst);
    asm volatile("cp.async.cg.shared.global [%0], [%1], 16;" :: "r"(a), "l"(src));
}

// ---------------- init ------------------------------------------------------
__global__ void k_init() {
    int i = blockIdx.x * blockDim.x + threadIdx.x;
    if (i < HSLOT) g_hs_buf[i] = 0.0f;          // h0 = 0
    if (i == 0) { g_arrive = 0u; g_epoch = 0u; }
}

// ---------------- kernel A: embed gather + x-projection GEMM ---------------
__global__ __launch_bounds__(256) void k_xproj(
    const int* __restrict__ idx, const float* __restrict__ emb,
    const float* __restrict__ wx0, const float* __restrict__ wx1,
    const float* __restrict__ wx2, const float* __restrict__ wx3,
    const float* __restrict__ bb0, const float* __restrict__ bb1,
    const float* __restrict__ bb2, const float* __restrict__ bb3)
{
    __shared__ float As[16][128];
    __shared__ float Bs[16][128];
    __shared__ int   idx_s[128];
    const int tid = threadIdx.x;
    const int bx = blockIdx.x;           // 0..15
    const int by = blockIdx.y;           // 0..127
    const int gate = bx >> 2;
    const int jj0  = (bx & 3) * 128;
    const float* wB = (gate == 0) ? wx0 : (gate == 1) ? wx1 : (gate == 2) ? wx2 : wx3;
    const float* bB = (gate == 0) ? bb0 : (gate == 1) ? bb1 : (gate == 2) ? bb2 : bb3;

    if (tid < 128) idx_s[tid] = idx[by * 128 + tid];
    __syncthreads();

    const int ty = tid >> 4, tx = tid & 15;
    float acc[8][8] = {};

    const int am  = tid >> 2;
    const int akv = (tid & 3) * 4;
    const int br  = tid >> 5;
    const int bcv = (tid & 31) * 4;

    for (int k0 = 0; k0 < EMBED; k0 += 16) {
        #pragma unroll
        for (int i = 0; i < 2; i++) {
            int m = am + 64 * i;
            float4 v = *(const float4*)(emb + (size_t)idx_s[m] * EMBED + k0 + akv);
            As[akv + 0][m] = v.x; As[akv + 1][m] = v.y;
            As[akv + 2][m] = v.z; As[akv + 3][m] = v.w;
        }
        #pragma unroll
        for (int i = 0; i < 2; i++) {
            int r = br + 8 * i;
            *(float4*)&Bs[r][bcv] =
                *(const float4*)(wB + (size_t)(k0 + r) * HIDDEN + jj0 + bcv);
        }
        __syncthreads();
        #pragma unroll
        for (int kk = 0; kk < 16; kk++) {
            float a[8], b[8];
            *(float4*)&a[0] = *(const float4*)&As[kk][ty * 8];
            *(float4*)&a[4] = *(const float4*)&As[kk][ty * 8 + 4];
            *(float4*)&b[0] = *(const float4*)&Bs[kk][tx * 8];
            *(float4*)&b[4] = *(const float4*)&Bs[kk][tx * 8 + 4];
            #pragma unroll
            for (int i = 0; i < 8; i++)
                #pragma unroll
                for (int j = 0; j < 8; j++)
                    acc[i][j] = fmaf(a[i], b[j], acc[i][j]);
        }
        __syncthreads();
    }

    float bv[8];
    #pragma unroll
    for (int j = 0; j < 8; j++) bv[j] = bB[jj0 + tx * 8 + j];
    #pragma unroll
    for (int i = 0; i < 8; i++) {
        size_t row = (size_t)by * 128 + ty * 8 + i;
        float* o = g_xproj + row * G4 + gate * HIDDEN + jj0 + tx * 8;
        #pragma unroll
        for (int j = 0; j < 8; j++) o[j] = acc[i][j] + bv[j];
    }
}

// ---------------- persistent LSTM recurrence kernel -------------------------
// 128 CTAs x 256 threads. CTA ci owns hidden cols e0=ci*4..e0+3 for ALL gates.
// SMEM: Wsm2 [4g][512k][4e] f32x2-pairs | Hs [2buf][8kg][16kk][64b] |
//       Psum [8kg][4g][64b][5pad] | Xs [4g][64b][4j]
#define SM_W   0
#define SM_H   65536
#define SM_P   131072
#define SM_X   172032
#define SM_TOT 176128
#define PJ     5

__global__ __launch_bounds__(256, 1) void k_lstm(
    const float* __restrict__ wh0, const float* __restrict__ wh1,
    const float* __restrict__ wh2, const float* __restrict__ wh3)
{
    extern __shared__ char smem[];
    ull*   Wsm2 = (ull*)(smem + SM_W);
    float* Hs   = (float*)(smem + SM_H);
    float* Psum = (float*)(smem + SM_P);
    float* Xs   = (float*)(smem + SM_X);

    const int tid = threadIdx.x;
    const int ci  = blockIdx.x;
    const int e0  = ci * 4;

    // ---- load weight slice, pre-packed as (w,w) pairs ----
    for (int i = tid; i < 4 * 512; i += NTHR) {
        int g = i >> 9, k = i & 511;
        const float* w = (g == 0) ? wh0 : (g == 1) ? wh1 : (g == 2) ? wh2 : wh3;
        float4 v = *(const float4*)(w + (size_t)k * HIDDEN + e0);
        ull* dst = Wsm2 + (size_t)i * 4;
        dst[0] = pk2(v.x); dst[1] = pk2(v.y); dst[2] = pk2(v.z); dst[3] = pk2(v.w);
    }

    // compute-role indices: 8 k-groups x (4 gates x 8 b-quads)
    const int kg   = tid >> 5;
    const int gate = (tid >> 3) & 3;
    const int b0   = (tid & 7) * 8;
    // epilogue-role indices
    const int ej = tid >> 6;       // 0..3
    const int eb = tid & 63;       // 0..63
    float c_reg = 0.0f;

    // staging map (8 float4 per thread per chunk)
    int st_b4[8], st_kk[8], st_kg[8];
    #pragma unroll
    for (int i = 0; i < 8; i++) {
        int lin = tid + NTHR * i;
        st_b4[i] = lin & 15; st_kk[i] = (lin >> 4) & 15; st_kg[i] = lin >> 8;
    }
    __syncthreads();

    for (int s = 0; s < SEQ; s++) {
        const float* hsrc = g_hs_buf + (size_t)s * HSLOT;

        // prefetch xproj slice for the epilogue
        {
            int g = tid >> 6, b = tid & 63;
            const float* src = g_xproj + ((size_t)(s * BATCH + b)) * G4 + g * HIDDEN + e0;
            cp_async16(&Xs[(g * 64 + b) * 4], src);
        }
        // stage chunk 0
        #pragma unroll
        for (int i = 0; i < 8; i++)
            cp_async16(Hs + (st_kg[i] * 16 + st_kk[i]) * 64 + st_b4[i] * 4,
                       hsrc + (st_kg[i] * 64 + st_kk[i]) * 64 + st_b4[i] * 4);
        asm volatile("cp.async.commit_group;\n" ::: "memory");

        ull acc[16];
        #pragma unroll
        for (int i = 0; i < 16; i++) acc[i] = 0ull;

        for (int ch = 0; ch < 4; ch++) {
            if (ch < 3) {
                float* hb = Hs + ((ch + 1) & 1) * 8192;
                #pragma unroll
                for (int i = 0; i < 8; i++)
                    cp_async16(hb + (st_kg[i] * 16 + st_kk[i]) * 64 + st_b4[i] * 4,
                               hsrc + (st_kg[i] * 64 + (ch + 1) * 16 + st_kk[i]) * 64 + st_b4[i] * 4);
                asm volatile("cp.async.commit_group;\n" ::: "memory");
                asm volatile("cp.async.wait_group 1;\n" ::: "memory");
            } else {
                asm volatile("cp.async.wait_group 0;\n" ::: "memory");
            }
            __syncthreads();

            const float* hb = Hs + (ch & 1) * 8192 + kg * 16 * 64 + b0;
            const ull*   wb = Wsm2 + ((size_t)(gate * 512 + kg * 64 + ch * 16)) * 4;
            #pragma unroll
            for (int kk = 0; kk < 16; kk++) {
                ulonglong2 wA = *(const ulonglong2*)(wb + kk * 4);
                ulonglong2 wB = *(const ulonglong2*)(wb + kk * 4 + 2);
                ulonglong2 h01 = *(const ulonglong2*)(hb + kk * 64);
                ulonglong2 h23 = *(const ulonglong2*)(hb + kk * 64 + 4);
                fma2(acc[0],  h01.x, wA.x); fma2(acc[1],  h01.y, wA.x);
                fma2(acc[2],  h23.x, wA.x); fma2(acc[3],  h23.y, wA.x);
                fma2(acc[4],  h01.x, wA.y); fma2(acc[5],  h01.y, wA.y);
                fma2(acc[6],  h23.x, wA.y); fma2(acc[7],  h23.y, wA.y);
                fma2(acc[8],  h01.x, wB.x); fma2(acc[9],  h01.y, wB.x);
                fma2(acc[10], h23.x, wB.x); fma2(acc[11], h23.y, wB.x);
                fma2(acc[12], h01.x, wB.y); fma2(acc[13], h01.y, wB.y);
                fma2(acc[14], h23.x, wB.y); fma2(acc[15], h23.y, wB.y);
            }
            __syncthreads();
        }

        // write partial sums: acc[e*4+p] holds (b0+2p, b0+2p+1) for col e
        #pragma unroll
        for (int e = 0; e < 4; e++)
            #pragma unroll
            for (int p = 0; p < 4; p++) {
                float lo, hi; unpk(acc[e * 4 + p], lo, hi);
                Psum[((kg * 4 + gate) * 64 + b0 + 2 * p)     * PJ + e] = lo;
                Psum[((kg * 4 + gate) * 64 + b0 + 2 * p + 1) * PJ + e] = hi;
            }
        __syncthreads();

        // epilogue: thread (eb, ej) owns hidden col e0+ej, batch eb
        float gi = Xs[(0 * 64 + eb) * 4 + ej];
        float gf = Xs[(1 * 64 + eb) * 4 + ej];
        float gc = Xs[(2 * 64 + eb) * 4 + ej];
        float go = Xs[(3 * 64 + eb) * 4 + ej];
        #pragma unroll
        for (int q = 0; q < 8; q++) {
            gi += Psum[((q * 4 + 0) * 64 + eb) * PJ + ej];
            gf += Psum[((q * 4 + 1) * 64 + eb) * PJ + ej];
            gc += Psum[((q * 4 + 2) * 64 + eb) * PJ + ej];
            go += Psum[((q * 4 + 3) * 64 + eb) * PJ + ej];
        }
        c_reg = sigf(gf) * c_reg + sigf(gi) * tanhx(gc);
        float hval = sigf(go) * tanhx(c_reg);
        g_hs_buf[(size_t)(s + 1) * HSLOT + (e0 + ej) * 64 + eb] = hval;

        // grid barrier
        __threadfence();
        __syncthreads();
        if (tid == 0) {
            unsigned a = atomicAdd(&g_arrive, 1u);
            if (a == (unsigned)(gridDim.x - 1)) {
                atomicExch(&g_arrive, 0u);
                __threadfence();
                g_epoch = (unsigned)(s + 1);
            } else {
                while (g_epoch < (unsigned)(s + 1)) __nanosleep(64);
            }
            __threadfence();
        }
        __syncthreads();
    }

    // final c state
    g_c[eb * HIDDEN + e0 + ej] = c_reg;
}

// ---------------- kernel C: output projection GEMM -------------------------
__global__ __launch_bounds__(256) void k_out(
    const float* __restrict__ wy, const float* __restrict__ byv,
    float* __restrict__ out)
{
    __shared__ float As[16][128];
    __shared__ float Bs[16][128];
    const int tid = threadIdx.x;
    const int bx = blockIdx.x;   // 0..78
    const int by = blockIdx.y;   // 0..127
    const int n0 = bx * 128;
    const int ty = tid >> 4, tx = tid & 15;
    float acc[8][8] = {};

    const int ar  = tid >> 5;          // 0..7
    const int am4 = (tid & 31) * 4;    // 0..124
    const int br  = tid >> 5;
    const int bcv = (tid & 31) * 4;

    for (int k0 = 0; k0 < HIDDEN; k0 += 16) {
        #pragma unroll
        for (int i = 0; i < 2; i++) {
            int kk = ar + 8 * i;
            int m  = am4;
            int sidx = (by * 128 + m) >> 6;      // all 4 m's same s
            int b    = m & 63;
            float4 v = *(const float4*)(g_hs_buf +
                        (size_t)(sidx + 1) * HSLOT + (k0 + kk) * 64 + b);
            *(float4*)&As[kk][m] = v;
        }
        #pragma unroll
        for (int i = 0; i < 2; i++) {
            int r = br + 8 * i;
            int col = n0 + bcv;
            float4 v = make_float4(0.f, 0.f, 0.f, 0.f);
            if (col < VOCAB)
                v = *(const float4*)(wy + (size_t)(k0 + r) * VOCAB + col);
            *(float4*)&Bs[r][bcv] = v;
        }
        __syncthreads();
        #pragma unroll
        for (int kk = 0; kk < 16; kk++) {
            float a[8], b[8];
            *(float4*)&a[0] = *(const float4*)&As[kk][ty * 8];
            *(float4*)&a[4] = *(const float4*)&As[kk][ty * 8 + 4];
            *(float4*)&b[0] = *(const float4*)&Bs[kk][tx * 8];
            *(float4*)&b[4] = *(const float4*)&Bs[kk][tx * 8 + 4];
            #pragma unroll
            for (int i = 0; i < 8; i++)
                #pragma unroll
                for (int j = 0; j < 8; j++)
                    acc[i][j] = fmaf(a[i], b[j], acc[i][j]);
        }
        __syncthreads();
    }

    int colb = n0 + tx * 8;
    if (colb + 8 <= VOCAB) {
        float bv[8];
        #pragma unroll
        for (int j = 0; j < 8; j++) bv[j] = byv[colb + j];
        #pragma unroll
        for (int i = 0; i < 8; i++) {
            size_t row = (size_t)by * 128 + ty * 8 + i;
            float* o = out + row * VOCAB + colb;
            #pragma unroll
            for (int j = 0; j < 8; j++) o[j] = acc[i][j] + bv[j];
        }
    }
}

// ---------------- tail: ht, ct ---------------------------------------------
__global__ void k_tail(float* out) {
    int i = blockIdx.x * blockDim.x + threadIdx.x;
    size_t base = (size_t)ROWS * VOCAB;
    if (i < BATCH * HIDDEN) {
        int b = i >> 9, e = i & 511;
        out[base + i] = g_hs_buf[(size_t)SEQ * HSLOT + e * 64 + b];
    } else if (i < 2 * BATCH * HIDDEN) {
        out[base + i] = g_c[i - BATCH * HIDDEN];
    }
}

// ---------------- launch ----------------------------------------------------
extern "C" void kernel_launch(void* const* d_in, const int* in_sizes, int n_in,
                              void* d_out, int out_size) {
    const int*   input_ = (const int*)  d_in[0];
    const float* emb    = (const float*)d_in[1];
    const float* wxi    = (const float*)d_in[2];
    const float* whi    = (const float*)d_in[3];
    const float* bi     = (const float*)d_in[4];
    const float* wxf    = (const float*)d_in[5];
    const float* whf    = (const float*)d_in[6];
    const float* bf     = (const float*)d_in[7];
    const float* wxc    = (const float*)d_in[8];
    const float* whc    = (const float*)d_in[9];
    const float* bc     = (const float*)d_in[10];
    const float* wxo    = (const float*)d_in[11];
    const float* who    = (const float*)d_in[12];
    const float* bo     = (const float*)d_in[13];
    const float* wy     = (const float*)d_in[14];
    const float* by     = (const float*)d_in[15];
    float* out = (float*)d_out;

    static bool attr_set = false;
    if (!attr_set) {
        cudaFuncSetAttribute(k_lstm, cudaFuncAttributeMaxDynamicSharedMemorySize, SM_TOT);
        attr_set = true;
    }

    k_init<<<NCTA, NTHR>>>();

    dim3 gA(16, 128);
    k_xproj<<<gA, 256>>>(input_, emb, wxi, wxf, wxc, wxo, bi, bf, bc, bo);

    k_lstm<<<NCTA, NTHR, SM_TOT>>>(whi, whf, whc, who);

    dim3 gC(79, 128);
    k_out<<<gC, 256>>>(wy, by, out);

    if ((long long)out_size >= (long long)ROWS * VOCAB + 2LL * BATCH * HIDDEN)
        k_tail<<<(2 * BATCH * HIDDEN + 255) / 256, 256>>>(out);
}

// round 3
// speedup vs baseline: 1.1105x; 1.0099x over previous
#include <cuda_runtime.h>
#include <math.h>

#define SEQ    256
#define BATCH  64
#define EMBED  512
#define HIDDEN 512
#define VOCAB  10000
#define ROWS   (SEQ*BATCH)      /* 16384 */
#define G4     (4*HIDDEN)       /* 2048  */
#define NCTA   128
#define NTHR   256
#define HSLOT  (HIDDEN*BATCH)   /* 32768 floats per h slot */

typedef unsigned long long ull;

// ---------------- scratch (static device globals) ---------------------------
__device__ float g_xproj[(size_t)ROWS * G4];              // [row][2048], bias folded
__device__ __align__(16) float g_hs_buf[(size_t)(SEQ + 1) * HSLOT];  // [s][k][b] transposed
__device__ float g_c[BATCH * HIDDEN];
__device__ unsigned g_arrive;
__device__ volatile unsigned g_epoch;

__device__ __forceinline__ float sigf(float x)  { return 1.0f / (1.0f + __expf(-x)); }
__device__ __forceinline__ float tanhx(float x) { return 2.0f / (1.0f + __expf(-2.0f * x)) - 1.0f; }

__device__ __forceinline__ ull pk2(float x) {
    ull r; asm("mov.b64 %0, {%1, %2};" : "=l"(r) : "f"(x), "f"(x)); return r;
}
__device__ __forceinline__ void unpk(ull v, float& lo, float& hi) {
    asm("mov.b64 {%0, %1}, %2;" : "=f"(lo), "=f"(hi) : "l"(v));
}
__device__ __forceinline__ void fma2(ull& d, ull a, ull b) {
    asm("fma.rn.f32x2 %0, %1, %2, %0;" : "+l"(d) : "l"(a), "l"(b));
}
__device__ __forceinline__ void cp_async16(void* dst, const void* src) {
    unsigned a = (unsigned)__cvta_generic_to_shared(dst);
    asm volatile("cp.async.cg.shared.global [%0], [%1], 16;" :: "r"(a), "l"(src));
}

// ---------------- init ------------------------------------------------------
__global__ void k_init() {
    int i = blockIdx.x * blockDim.x + threadIdx.x;
    if (i < HSLOT) g_hs_buf[i] = 0.0f;          // h0 = 0
    if (i == 0) { g_arrive = 0u; g_epoch = 0u; }
}

// ---------------- kernel A: embed gather + x-projection GEMM ---------------
// FFMA2 inner loop: acc pairs over j.
__global__ __launch_bounds__(256) void k_xproj(
    const int* __restrict__ idx, const float* __restrict__ emb,
    const float* __restrict__ wx0, const float* __restrict__ wx1,
    const float* __restrict__ wx2, const float* __restrict__ wx3,
    const float* __restrict__ bb0, const float* __restrict__ bb1,
    const float* __restrict__ bb2, const float* __restrict__ bb3)
{
    __shared__ float As[16][128];
    __shared__ __align__(16) float Bs[16][128];
    __shared__ int   idx_s[128];
    const int tid = threadIdx.x;
    const int bx = blockIdx.x;           // 0..15
    const int by = blockIdx.y;           // 0..127
    const int gate = bx >> 2;
    const int jj0  = (bx & 3) * 128;
    const float* wB = (gate == 0) ? wx0 : (gate == 1) ? wx1 : (gate == 2) ? wx2 : wx3;
    const float* bB = (gate == 0) ? bb0 : (gate == 1) ? bb1 : (gate == 2) ? bb2 : bb3;

    if (tid < 128) idx_s[tid] = idx[by * 128 + tid];
    __syncthreads();

    const int ty = tid >> 4, tx = tid & 15;
    ull acc2[8][4];
    #pragma unroll
    for (int i = 0; i < 8; i++)
        #pragma unroll
        for (int j = 0; j < 4; j++) acc2[i][j] = 0ull;

    const int am  = tid >> 2;
    const int akv = (tid & 3) * 4;
    const int br  = tid >> 5;
    const int bcv = (tid & 31) * 4;

    for (int k0 = 0; k0 < EMBED; k0 += 16) {
        #pragma unroll
        for (int i = 0; i < 2; i++) {
            int m = am + 64 * i;
            float4 v = *(const float4*)(emb + (size_t)idx_s[m] * EMBED + k0 + akv);
            As[akv + 0][m] = v.x; As[akv + 1][m] = v.y;
            As[akv + 2][m] = v.z; As[akv + 3][m] = v.w;
        }
        #pragma unroll
        for (int i = 0; i < 2; i++) {
            int r = br + 8 * i;
            *(float4*)&Bs[r][bcv] =
                *(const float4*)(wB + (size_t)(k0 + r) * HIDDEN + jj0 + bcv);
        }
        __syncthreads();
        #pragma unroll
        for (int kk = 0; kk < 16; kk++) {
            float a[8];
            *(float4*)&a[0] = *(const float4*)&As[kk][ty * 8];
            *(float4*)&a[4] = *(const float4*)&As[kk][ty * 8 + 4];
            ulonglong2 t0 = *(const ulonglong2*)&Bs[kk][tx * 8];
            ulonglong2 t1 = *(const ulonglong2*)&Bs[kk][tx * 8 + 4];
            #pragma unroll
            for (int i = 0; i < 8; i++) {
                ull ap = pk2(a[i]);
                fma2(acc2[i][0], ap, t0.x);
                fma2(acc2[i][1], ap, t0.y);
                fma2(acc2[i][2], ap, t1.x);
                fma2(acc2[i][3], ap, t1.y);
            }
        }
        __syncthreads();
    }

    float bv[8];
    #pragma unroll
    for (int j = 0; j < 8; j++) bv[j] = bB[jj0 + tx * 8 + j];
    #pragma unroll
    for (int i = 0; i < 8; i++) {
        size_t row = (size_t)by * 128 + ty * 8 + i;
        float* o = g_xproj + row * G4 + gate * HIDDEN + jj0 + tx * 8;
        #pragma unroll
        for (int jp = 0; jp < 4; jp++) {
            float lo, hi; unpk(acc2[i][jp], lo, hi);
            o[2 * jp]     = lo + bv[2 * jp];
            o[2 * jp + 1] = hi + bv[2 * jp + 1];
        }
    }
}

// ---------------- persistent LSTM recurrence kernel -------------------------
#define SM_W   0
#define SM_H   65536
#define SM_P   131072
#define SM_X   172032
#define SM_TOT 176128
#define PJ     5

__global__ __launch_bounds__(256, 1) void k_lstm(
    const float* __restrict__ wh0, const float* __restrict__ wh1,
    const float* __restrict__ wh2, const float* __restrict__ wh3)
{
    extern __shared__ char smem[];
    ull*   Wsm2 = (ull*)(smem + SM_W);
    float* Hs   = (float*)(smem + SM_H);
    float* Psum = (float*)(smem + SM_P);
    float* Xs   = (float*)(smem + SM_X);

    const int tid = threadIdx.x;
    const int ci  = blockIdx.x;
    const int e0  = ci * 4;

    for (int i = tid; i < 4 * 512; i += NTHR) {
        int g = i >> 9, k = i & 511;
        const float* w = (g == 0) ? wh0 : (g == 1) ? wh1 : (g == 2) ? wh2 : wh3;
        float4 v = *(const float4*)(w + (size_t)k * HIDDEN + e0);
        ull* dst = Wsm2 + (size_t)i * 4;
        dst[0] = pk2(v.x); dst[1] = pk2(v.y); dst[2] = pk2(v.z); dst[3] = pk2(v.w);
    }

    const int kg   = tid >> 5;
    const int gate = (tid >> 3) & 3;
    const int b0   = (tid & 7) * 8;
    const int ej = tid >> 6;       // 0..3
    const int eb = tid & 63;       // 0..63
    float c_reg = 0.0f;

    int st_b4[8], st_kk[8], st_kg[8];
    #pragma unroll
    for (int i = 0; i < 8; i++) {
        int lin = tid + NTHR * i;
        st_b4[i] = lin & 15; st_kk[i] = (lin >> 4) & 15; st_kg[i] = lin >> 8;
    }
    __syncthreads();

    for (int s = 0; s < SEQ; s++) {
        const float* hsrc = g_hs_buf + (size_t)s * HSLOT;

        {
            int g = tid >> 6, b = tid & 63;
            const float* src = g_xproj + ((size_t)(s * BATCH + b)) * G4 + g * HIDDEN + e0;
            cp_async16(&Xs[(g * 64 + b) * 4], src);
        }
        #pragma unroll
        for (int i = 0; i < 8; i++)
            cp_async16(Hs + (st_kg[i] * 16 + st_kk[i]) * 64 + st_b4[i] * 4,
                       hsrc + (st_kg[i] * 64 + st_kk[i]) * 64 + st_b4[i] * 4);
        asm volatile("cp.async.commit_group;\n" ::: "memory");

        ull acc[16];
        #pragma unroll
        for (int i = 0; i < 16; i++) acc[i] = 0ull;

        for (int ch = 0; ch < 4; ch++) {
            if (ch < 3) {
                float* hb = Hs + ((ch + 1) & 1) * 8192;
                #pragma unroll
                for (int i = 0; i < 8; i++)
                    cp_async16(hb + (st_kg[i] * 16 + st_kk[i]) * 64 + st_b4[i] * 4,
                               hsrc + (st_kg[i] * 64 + (ch + 1) * 16 + st_kk[i]) * 64 + st_b4[i] * 4);
                asm volatile("cp.async.commit_group;\n" ::: "memory");
                asm volatile("cp.async.wait_group 1;\n" ::: "memory");
            } else {
                asm volatile("cp.async.wait_group 0;\n" ::: "memory");
            }
            __syncthreads();

            const float* hb = Hs + (ch & 1) * 8192 + kg * 16 * 64 + b0;
            const ull*   wb = Wsm2 + ((size_t)(gate * 512 + kg * 64 + ch * 16)) * 4;
            #pragma unroll
            for (int kk = 0; kk < 16; kk++) {
                ulonglong2 wA = *(const ulonglong2*)(wb + kk * 4);
                ulonglong2 wB = *(const ulonglong2*)(wb + kk * 4 + 2);
                ulonglong2 h01 = *(const ulonglong2*)(hb + kk * 64);
                ulonglong2 h23 = *(const ulonglong2*)(hb + kk * 64 + 4);
                fma2(acc[0],  h01.x, wA.x); fma2(acc[1],  h01.y, wA.x);
                fma2(acc[2],  h23.x, wA.x); fma2(acc[3],  h23.y, wA.x);
                fma2(acc[4],  h01.x, wA.y); fma2(acc[5],  h01.y, wA.y);
                fma2(acc[6],  h23.x, wA.y); fma2(acc[7],  h23.y, wA.y);
                fma2(acc[8],  h01.x, wB.x); fma2(acc[9],  h01.y, wB.x);
                fma2(acc[10], h23.x, wB.x); fma2(acc[11], h23.y, wB.x);
                fma2(acc[12], h01.x, wB.y); fma2(acc[13], h01.y, wB.y);
                fma2(acc[14], h23.x, wB.y); fma2(acc[15], h23.y, wB.y);
            }
            __syncthreads();
        }

        #pragma unroll
        for (int e = 0; e < 4; e++)
            #pragma unroll
            for (int p = 0; p < 4; p++) {
                float lo, hi; unpk(acc[e * 4 + p], lo, hi);
                Psum[((kg * 4 + gate) * 64 + b0 + 2 * p)     * PJ + e] = lo;
                Psum[((kg * 4 + gate) * 64 + b0 + 2 * p + 1) * PJ + e] = hi;
            }
        __syncthreads();

        float gi = Xs[(0 * 64 + eb) * 4 + ej];
        float gf = Xs[(1 * 64 + eb) * 4 + ej];
        float gc = Xs[(2 * 64 + eb) * 4 + ej];
        float go = Xs[(3 * 64 + eb) * 4 + ej];
        #pragma unroll
        for (int q = 0; q < 8; q++) {
            gi += Psum[((q * 4 + 0) * 64 + eb) * PJ + ej];
            gf += Psum[((q * 4 + 1) * 64 + eb) * PJ + ej];
            gc += Psum[((q * 4 + 2) * 64 + eb) * PJ + ej];
            go += Psum[((q * 4 + 3) * 64 + eb) * PJ + ej];
        }
        c_reg = sigf(gf) * c_reg + sigf(gi) * tanhx(gc);
        float hval = sigf(go) * tanhx(c_reg);
        g_hs_buf[(size_t)(s + 1) * HSLOT + (e0 + ej) * 64 + eb] = hval;

        __threadfence();
        __syncthreads();
        if (tid == 0) {
            unsigned a = atomicAdd(&g_arrive, 1u);
            if (a == (unsigned)(gridDim.x - 1)) {
                atomicExch(&g_arrive, 0u);
                __threadfence();
                g_epoch = (unsigned)(s + 1);
            } else {
                while (g_epoch < (unsigned)(s + 1)) __nanosleep(64);
            }
            __threadfence();
        }
        __syncthreads();
    }

    g_c[eb * HIDDEN + e0 + ej] = c_reg;
}

// ---------------- kernel C: output projection GEMM (FFMA2) ------------------
__global__ __launch_bounds__(256) void k_out(
    const float* __restrict__ wy, const float* __restrict__ byv,
    float* __restrict__ out)
{
    __shared__ float As[16][128];
    __shared__ __align__(16) float Bs[16][128];
    const int tid = threadIdx.x;
    const int bx = blockIdx.x;   // 0..78
    const int by = blockIdx.y;   // 0..127
    const int n0 = bx * 128;
    const int ty = tid >> 4, tx = tid & 15;
    ull acc2[8][4];
    #pragma unroll
    for (int i = 0; i < 8; i++)
        #pragma unroll
        for (int j = 0; j < 4; j++) acc2[i][j] = 0ull;

    const int ar  = tid >> 5;          // 0..7
    const int am4 = (tid & 31) * 4;    // 0..124
    const int br  = tid >> 5;
    const int bcv = (tid & 31) * 4;

    for (int k0 = 0; k0 < HIDDEN; k0 += 16) {
        #pragma unroll
        for (int i = 0; i < 2; i++) {
            int kk = ar + 8 * i;
            int m  = am4;
            int sidx = (by * 128 + m) >> 6;      // all 4 m's same s
            int b    = m & 63;
            float4 v = *(const float4*)(g_hs_buf +
                        (size_t)(sidx + 1) * HSLOT + (k0 + kk) * 64 + b);
            *(float4*)&As[kk][m] = v;
        }
        #pragma unroll
        for (int i = 0; i < 2; i++) {
            int r = br + 8 * i;
            int col = n0 + bcv;
            float4 v = make_float4(0.f, 0.f, 0.f, 0.f);
            if (col < VOCAB)
                v = *(const float4*)(wy + (size_t)(k0 + r) * VOCAB + col);
            *(float4*)&Bs[r][bcv] = v;
        }
        __syncthreads();
        #pragma unroll
        for (int kk = 0; kk < 16; kk++) {
            float a[8];
            *(float4*)&a[0] = *(const float4*)&As[kk][ty * 8];
            *(float4*)&a[4] = *(const float4*)&As[kk][ty * 8 + 4];
            ulonglong2 t0 = *(const ulonglong2*)&Bs[kk][tx * 8];
            ulonglong2 t1 = *(const ulonglong2*)&Bs[kk][tx * 8 + 4];
            #pragma unroll
            for (int i = 0; i < 8; i++) {
                ull ap = pk2(a[i]);
                fma2(acc2[i][0], ap, t0.x);
                fma2(acc2[i][1], ap, t0.y);
                fma2(acc2[i][2], ap, t1.x);
                fma2(acc2[i][3], ap, t1.y);
            }
        }
        __syncthreads();
    }

    int colb = n0 + tx * 8;
    if (colb + 8 <= VOCAB) {
        float bv[8];
        #pragma unroll
        for (int j = 0; j < 8; j++) bv[j] = byv[colb + j];
        #pragma unroll
        for (int i = 0; i < 8; i++) {
            size_t row = (size_t)by * 128 + ty * 8 + i;
            float* o = out + row * VOCAB + colb;
            #pragma unroll
            for (int jp = 0; jp < 4; jp++) {
                float lo, hi; unpk(acc2[i][jp], lo, hi);
                o[2 * jp]     = lo + bv[2 * jp];
                o[2 * jp + 1] = hi + bv[2 * jp + 1];
            }
        }
    }
}

// ---------------- tail: ht, ct ---------------------------------------------
__global__ void k_tail(float* out) {
    int i = blockIdx.x * blockDim.x + threadIdx.x;
    size_t base = (size_t)ROWS * VOCAB;
    if (i < BATCH * HIDDEN) {
        int b = i >> 9, e = i & 511;
        out[base + i] = g_hs_buf[(size_t)SEQ * HSLOT + e * 64 + b];
    } else if (i < 2 * BATCH * HIDDEN) {
        out[base + i] = g_c[i - BATCH * HIDDEN];
    }
}

// ---------------- launch ----------------------------------------------------
extern "C" void kernel_launch(void* const* d_in, const int* in_sizes, int n_in,
                              void* d_out, int out_size) {
    const int*   input_ = (const int*)  d_in[0];
    const float* emb    = (const float*)d_in[1];
    const float* wxi    = (const float*)d_in[2];
    const float* whi    = (const float*)d_in[3];
    const float* bi     = (const float*)d_in[4];
    const float* wxf    = (const float*)d_in[5];
    const float* whf    = (const float*)d_in[6];
    const float* bf     = (const float*)d_in[7];
    const float* wxc    = (const float*)d_in[8];
    const float* whc    = (const float*)d_in[9];
    const float* bc     = (const float*)d_in[10];
    const float* wxo    = (const float*)d_in[11];
    const float* who    = (const float*)d_in[12];
    const float* bo     = (const float*)d_in[13];
    const float* wy     = (const float*)d_in[14];
    const float* by     = (const float*)d_in[15];
    float* out = (float*)d_out;

    static bool attr_set = false;
    if (!attr_set) {
        cudaFuncSetAttribute(k_lstm, cudaFuncAttributeMaxDynamicSharedMemorySize, SM_TOT);
        attr_set = true;
    }

    k_init<<<NCTA, NTHR>>>();

    dim3 gA(16, 128);
    k_xproj<<<gA, 256>>>(input_, emb, wxi, wxf, wxc, wxo, bi, bf, bc, bo);

    k_lstm<<<NCTA, NTHR, SM_TOT>>>(whi, whf, whc, who);

    dim3 gC(79, 128);
    k_out<<<gC, 256>>>(wy, by, out);

    if ((long long)out_size >= (long long)ROWS * VOCAB + 2LL * BATCH * HIDDEN)
        k_tail<<<(2 * BATCH * HIDDEN + 255) / 256, 256>>>(out);
}

// round 5
// speedup vs baseline: 1.7719x; 1.5956x over previous
#include <cuda_runtime.h>
#include <cuda_bf16.h>
#include <math.h>
#include <stdint.h>

#define SEQ    256
#define BATCH  64
#define EMBED  512
#define HIDDEN 512
#define VOCAB  10000
#define NPAD   10240
#define ROWS   (SEQ*BATCH)      /* 16384 */
#define G4     (4*HIDDEN)       /* 2048  */
#define NCTA   128
#define NTHR   256
#define HSLOT  (HIDDEN*BATCH)   /* 32768 floats per h slot */

typedef unsigned long long ull;

// ---------------- scratch (static device globals) ---------------------------
__device__ float g_xproj[(size_t)ROWS * G4];
__device__ __align__(16) float g_hs_buf[(size_t)(SEQ + 1) * HSLOT];  // [s][k][b]
__device__ float g_c[BATCH * HIDDEN];
__device__ float g_biasx[G4];
__device__ unsigned g_arrive;
__device__ volatile unsigned g_epoch;

// bf16 hi/lo planes for HMMA GEMMs (row-major [m][k] / [n][k], k=512)
__device__ __align__(16) __nv_bfloat16 A_emb_hi[(size_t)ROWS * EMBED];
__device__ __align__(16) __nv_bfloat16 A_emb_lo[(size_t)ROWS * EMBED];
__device__ __align__(16) __nv_bfloat16 A_hs_hi[(size_t)ROWS * HIDDEN];
__device__ __align__(16) __nv_bfloat16 A_hs_lo[(size_t)ROWS * HIDDEN];
__device__ __align__(16) __nv_bfloat16 Bx_hi[(size_t)G4 * EMBED];
__device__ __align__(16) __nv_bfloat16 Bx_lo[(size_t)G4 * EMBED];
__device__ __align__(16) __nv_bfloat16 By_hi[(size_t)NPAD * HIDDEN];
__device__ __align__(16) __nv_bfloat16 By_lo[(size_t)NPAD * HIDDEN];

__device__ __forceinline__ float sigf(float x)  { return 1.0f / (1.0f + __expf(-x)); }
__device__ __forceinline__ float tanhx(float x) { return 2.0f / (1.0f + __expf(-2.0f * x)) - 1.0f; }

__device__ __forceinline__ ull pk2(float x) {
    ull r; asm("mov.b64 %0, {%1, %2};" : "=l"(r) : "f"(x), "f"(x)); return r;
}
__device__ __forceinline__ void unpk(ull v, float& lo, float& hi) {
    asm("mov.b64 {%0, %1}, %2;" : "=f"(lo), "=f"(hi) : "l"(v));
}
__device__ __forceinline__ void fma2(ull& d, ull a, ull b) {
    asm("fma.rn.f32x2 %0, %1, %2, %0;" : "+l"(d) : "l"(a), "l"(b));
}
__device__ __forceinline__ void cp_async16(void* dst, const void* src) {
    unsigned a = (unsigned)__cvta_generic_to_shared(dst);
    asm volatile("cp.async.cg.shared.global [%0], [%1], 16;" :: "r"(a), "l"(src));
}

#define SWZ(o) ((o) ^ (((o) >> 3) & 0x70))

__device__ __forceinline__ void ldm4(uint32_t* r, uint32_t a) {
    asm volatile("ldmatrix.sync.aligned.m8n8.x4.shared.b16 {%0,%1,%2,%3}, [%4];"
        : "=r"(r[0]), "=r"(r[1]), "=r"(r[2]), "=r"(r[3]) : "r"(a));
}
__device__ __forceinline__ void mma16816(float* d, const uint32_t* a, const uint32_t* b) {
    asm volatile("mma.sync.aligned.m16n8k16.row.col.f32.bf16.bf16.f32 "
        "{%0,%1,%2,%3}, {%4,%5,%6,%7}, {%8,%9}, {%0,%1,%2,%3};"
        : "+f"(d[0]), "+f"(d[1]), "+f"(d[2]), "+f"(d[3])
        : "r"(a[0]), "r"(a[1]), "r"(a[2]), "r"(a[3]), "r"(b[0]), "r"(b[1]));
}

// ---------------- init ------------------------------------------------------
__global__ void k_init() {
    int i = blockIdx.x * blockDim.x + threadIdx.x;
    if (i < HSLOT) g_hs_buf[i] = 0.0f;
    if (i == 0) { g_arrive = 0u; g_epoch = 0u; }
}

// ---------------- convert kernels -------------------------------------------
__global__ void k_cvtA_emb(const int* __restrict__ idx, const float* __restrict__ emb) {
    size_t i = (size_t)blockIdx.x * 256 + threadIdx.x;   // ROWS*512
    int m = (int)(i >> 9), k = (int)(i & 511);
    float v = emb[(size_t)idx[m] * EMBED + k];
    __nv_bfloat16 h = __float2bfloat16(v);
    A_emb_hi[i] = h;
    A_emb_lo[i] = __float2bfloat16(v - __bfloat162float(h));
}

__global__ void k_cvtBx(const float* __restrict__ w0, const float* __restrict__ w1,
                        const float* __restrict__ w2, const float* __restrict__ w3,
                        const float* __restrict__ b0, const float* __restrict__ b1,
                        const float* __restrict__ b2, const float* __restrict__ b3) {
    int n = blockIdx.x * 256 + threadIdx.x;  // 0..2047
    int k = blockIdx.y;                      // 0..511
    int g = n >> 9, j = n & 511;
    const float* w = (g == 0) ? w0 : (g == 1) ? w1 : (g == 2) ? w2 : w3;
    float v = w[(size_t)k * HIDDEN + j];
    __nv_bfloat16 h = __float2bfloat16(v);
    Bx_hi[(size_t)n * 512 + k] = h;
    Bx_lo[(size_t)n * 512 + k] = __float2bfloat16(v - __bfloat162float(h));
    if (k == 0) {
        const float* bb = (g == 0) ? b0 : (g == 1) ? b1 : (g == 2) ? b2 : b3;
        g_biasx[n] = bb[j];
    }
}

__global__ void k_cvtBy(const float* __restrict__ wy) {
    int n = blockIdx.x * 256 + threadIdx.x;  // 0..10239
    int k = blockIdx.y;                      // 0..511
    float v = (n < VOCAB) ? wy[(size_t)k * VOCAB + n] : 0.0f;
    __nv_bfloat16 h = __float2bfloat16(v);
    By_hi[(size_t)n * 512 + k] = h;
    By_lo[(size_t)n * 512 + k] = __float2bfloat16(v - __bfloat162float(h));
}

// ---------------- HMMA GEMM: out[m][n] = A[m][:] . B[n][:] + bias[n] --------
// CTA tile 128m x 256n; 8 warps of 64x64; K in 8 chunks of 64.
// SMEM buf: Ahi 16K | Alo 16K | Bhi 32K | Blo 32K = 96K; double buffered.
#define GB_BUF 98304
#define GB_TOT 196608

__device__ __forceinline__ void gemm_hmma(
    const __nv_bfloat16* __restrict__ Ahi, const __nv_bfloat16* __restrict__ Alo,
    const __nv_bfloat16* __restrict__ Bhi, const __nv_bfloat16* __restrict__ Blo,
    const float* __restrict__ bias, float* __restrict__ out, int Ntot)
{
    extern __shared__ char sm[];
    const int tid = threadIdx.x;
    const int lid = tid & 31, wid = tid >> 5;
    const int mw = wid >> 2, nw = wid & 3;          // warp tile origin
    const int n0 = blockIdx.x * 256;
    const int m0 = blockIdx.y * 128;
    uint32_t smu = (uint32_t)__cvta_generic_to_shared(sm);

    float acc[4][8][4];
    #pragma unroll
    for (int a = 0; a < 4; a++)
        #pragma unroll
        for (int b = 0; b < 8; b++)
            #pragma unroll
            for (int c = 0; c < 4; c++) acc[a][b][c] = 0.0f;

    auto stage = [&](int c, int buf) {
        char* bb = sm + (size_t)buf * GB_BUF;
        #pragma unroll
        for (int it = 0; it < 24; it++) {
            int u = tid + it * 256;                  // 0..6143 16B-units
            const char* src; char* dst;
            if (u < 2048) {
                int plane = u >> 10, idx = u & 1023;
                int row = idx >> 3, kq = idx & 7;
                const __nv_bfloat16* Ap = plane ? Alo : Ahi;
                src = (const char*)(Ap + (((size_t)(m0 + row)) << 9) + c * 64 + kq * 8);
                dst = bb + plane * 16384 + SWZ(row * 128 + kq * 16);
            } else {
                int v = u - 2048;
                int plane = v >> 11, idx = v & 2047;
                int row = idx >> 3, kq = idx & 7;
                const __nv_bfloat16* Bp = plane ? Blo : Bhi;
                src = (const char*)(Bp + (((size_t)(n0 + row)) << 9) + c * 64 + kq * 8);
                dst = bb + 32768 + plane * 32768 + SWZ(row * 128 + kq * 16);
            }
            cp_async16(dst, src);
        }
        asm volatile("cp.async.commit_group;" ::: "memory");
    };

    stage(0, 0);
    for (int ch = 0; ch < 8; ch++) {
        if (ch + 1 < 8) {
            stage(ch + 1, (ch + 1) & 1);
            asm volatile("cp.async.wait_group 1;" ::: "memory");
        } else {
            asm volatile("cp.async.wait_group 0;" ::: "memory");
        }
        __syncthreads();

        uint32_t sb = smu + (uint32_t)(ch & 1) * GB_BUF;
        #pragma unroll
        for (int k16 = 0; k16 < 4; k16++) {
            int kb = k16 * 16;
            uint32_t ah[4][4], al[4][4];
            #pragma unroll
            for (int mt = 0; mt < 4; mt++) {
                uint32_t off = (uint32_t)((mw * 64 + mt * 16 + (lid & 15)) * 128
                              + kb * 2 + ((lid >> 4) & 1) * 16);
                ldm4(ah[mt], sb + SWZ(off));
                ldm4(al[mt], sb + 16384 + SWZ(off));
            }
            #pragma unroll
            for (int ntp = 0; ntp < 4; ntp++) {
                uint32_t offb = (uint32_t)((nw * 64 + ntp * 16 + ((lid >> 4) & 1) * 8
                               + (lid & 7)) * 128 + kb * 2 + ((lid >> 3) & 1) * 16);
                uint32_t bh[4], bl[4];
                ldm4(bh, sb + 32768 + SWZ(offb));
                ldm4(bl, sb + 65536 + SWZ(offb));
                #pragma unroll
                for (int mt = 0; mt < 4; mt++) {
                    mma16816(acc[mt][ntp * 2],     ah[mt], bh + 0);
                    mma16816(acc[mt][ntp * 2],     ah[mt], bl + 0);
                    mma16816(acc[mt][ntp * 2],     al[mt], bh + 0);
                    mma16816(acc[mt][ntp * 2 + 1], ah[mt], bh + 2);
                    mma16816(acc[mt][ntp * 2 + 1], ah[mt], bl + 2);
                    mma16816(acc[mt][ntp * 2 + 1], al[mt], bh + 2);
                }
            }
        }
        __syncthreads();
    }

    // epilogue: frag (c0,c1)=(m=l/4, n=2(l%4),+1), (c2,c3)=(m=l/4+8, same n)
    const int rq = lid >> 2, cp2 = (lid & 3) * 2;
    #pragma unroll
    for (int mt = 0; mt < 4; mt++) {
        int mrow = m0 + mw * 64 + mt * 16 + rq;
        float* o0 = out + (size_t)mrow * Ntot;
        float* o1 = out + (size_t)(mrow + 8) * Ntot;
        #pragma unroll
        for (int nt = 0; nt < 8; nt++) {
            int n = n0 + nw * 64 + nt * 8 + cp2;
            if (n < Ntot) {
                float b0v = bias[n], b1v = bias[n + 1];
                float2 v0 = make_float2(acc[mt][nt][0] + b0v, acc[mt][nt][1] + b1v);
                float2 v1 = make_float2(acc[mt][nt][2] + b0v, acc[mt][nt][3] + b1v);
                *(float2*)(o0 + n) = v0;
                *(float2*)(o1 + n) = v1;
            }
        }
    }
}

__global__ __launch_bounds__(256, 1) void k_gemm_x() {
    gemm_hmma(A_emb_hi, A_emb_lo, Bx_hi, Bx_lo, g_biasx, g_xproj, G4);
}
__global__ __launch_bounds__(256, 1) void k_gemm_o(const float* __restrict__ by,
                                                   float* __restrict__ out) {
    gemm_hmma(A_hs_hi, A_hs_lo, By_hi, By_lo, by, out, VOCAB);
}

// ---------------- persistent LSTM recurrence kernel -------------------------
#define SM_W   0
#define SM_H   65536
#define SM_P   131072
#define SM_X   172032
#define SM_TOT_L 176128
#define PJ     5

__global__ __launch_bounds__(256, 1) void k_lstm(
    const float* __restrict__ wh0, const float* __restrict__ wh1,
    const float* __restrict__ wh2, const float* __restrict__ wh3)
{
    extern __shared__ char smem[];
    ull*   Wsm2 = (ull*)(smem + SM_W);
    float* Hs   = (float*)(smem + SM_H);
    float* Psum = (float*)(smem + SM_P);
    float* Xs   = (float*)(smem + SM_X);

    const int tid = threadIdx.x;
    const int ci  = blockIdx.x;
    const int e0  = ci * 4;

    for (int i = tid; i < 4 * 512; i += NTHR) {
        int g = i >> 9, k = i & 511;
        const float* w = (g == 0) ? wh0 : (g == 1) ? wh1 : (g == 2) ? wh2 : wh3;
        float4 v = *(const float4*)(w + (size_t)k * HIDDEN + e0);
        ull* dst = Wsm2 + (size_t)i * 4;
        dst[0] = pk2(v.x); dst[1] = pk2(v.y); dst[2] = pk2(v.z); dst[3] = pk2(v.w);
    }

    const int kg   = tid >> 5;
    const int gate = (tid >> 3) & 3;
    const int b0   = (tid & 7) * 8;
    const int ej = tid >> 6;       // 0..3
    const int eb = tid & 63;       // 0..63
    float c_reg = 0.0f;

    int st_b4[8], st_kk[8], st_kg[8];
    #pragma unroll
    for (int i = 0; i < 8; i++) {
        int lin = tid + NTHR * i;
        st_b4[i] = lin & 15; st_kk[i] = (lin >> 4) & 15; st_kg[i] = lin >> 8;
    }
    __syncthreads();

    for (int s = 0; s < SEQ; s++) {
        const float* hsrc = g_hs_buf + (size_t)s * HSLOT;

        {
            int g = tid >> 6, b = tid & 63;
            const float* src = g_xproj + ((size_t)(s * BATCH + b)) * G4 + g * HIDDEN + e0;
            cp_async16(&Xs[(g * 64 + b) * 4], src);
        }
        #pragma unroll
        for (int i = 0; i < 8; i++)
            cp_async16(Hs + (st_kg[i] * 16 + st_kk[i]) * 64 + st_b4[i] * 4,
                       hsrc + (st_kg[i] * 64 + st_kk[i]) * 64 + st_b4[i] * 4);
        asm volatile("cp.async.commit_group;\n" ::: "memory");

        ull acc[16];
        #pragma unroll
        for (int i = 0; i < 16; i++) acc[i] = 0ull;

        for (int ch = 0; ch < 4; ch++) {
            if (ch < 3) {
                float* hb = Hs + ((ch + 1) & 1) * 8192;
                #pragma unroll
                for (int i = 0; i < 8; i++)
                    cp_async16(hb + (st_kg[i] * 16 + st_kk[i]) * 64 + st_b4[i] * 4,
                               hsrc + (st_kg[i] * 64 + (ch + 1) * 16 + st_kk[i]) * 64 + st_b4[i] * 4);
                asm volatile("cp.async.commit_group;\n" ::: "memory");
                asm volatile("cp.async.wait_group 1;\n" ::: "memory");
            } else {
                asm volatile("cp.async.wait_group 0;\n" ::: "memory");
            }
            __syncthreads();

            const float* hb = Hs + (ch & 1) * 8192 + kg * 16 * 64 + b0;
            const ull*   wb = Wsm2 + ((size_t)(gate * 512 + kg * 64 + ch * 16)) * 4;
            #pragma unroll
            for (int kk = 0; kk < 16; kk++) {
                ulonglong2 wA = *(const ulonglong2*)(wb + kk * 4);
                ulonglong2 wB = *(const ulonglong2*)(wb + kk * 4 + 2);
                ulonglong2 h01 = *(const ulonglong2*)(hb + kk * 64);
                ulonglong2 h23 = *(const ulonglong2*)(hb + kk * 64 + 4);
                fma2(acc[0],  h01.x, wA.x); fma2(acc[1],  h01.y, wA.x);
                fma2(acc[2],  h23.x, wA.x); fma2(acc[3],  h23.y, wA.x);
                fma2(acc[4],  h01.x, wA.y); fma2(acc[5],  h01.y, wA.y);
                fma2(acc[6],  h23.x, wA.y); fma2(acc[7],  h23.y, wA.y);
                fma2(acc[8],  h01.x, wB.x); fma2(acc[9],  h01.y, wB.x);
                fma2(acc[10], h23.x, wB.x); fma2(acc[11], h23.y, wB.x);
                fma2(acc[12], h01.x, wB.y); fma2(acc[13], h01.y, wB.y);
                fma2(acc[14], h23.x, wB.y); fma2(acc[15], h23.y, wB.y);
            }
            __syncthreads();
        }

        #pragma unroll
        for (int e = 0; e < 4; e++)
            #pragma unroll
            for (int p = 0; p < 4; p++) {
                float lo, hi; unpk(acc[e * 4 + p], lo, hi);
                Psum[((kg * 4 + gate) * 64 + b0 + 2 * p)     * PJ + e] = lo;
                Psum[((kg * 4 + gate) * 64 + b0 + 2 * p + 1) * PJ + e] = hi;
            }
        __syncthreads();

        float gi = Xs[(0 * 64 + eb) * 4 + ej];
        float gf = Xs[(1 * 64 + eb) * 4 + ej];
        float gc = Xs[(2 * 64 + eb) * 4 + ej];
        float go = Xs[(3 * 64 + eb) * 4 + ej];
        #pragma unroll
        for (int q = 0; q < 8; q++) {
            gi += Psum[((q * 4 + 0) * 64 + eb) * PJ + ej];
            gf += Psum[((q * 4 + 1) * 64 + eb) * PJ + ej];
            gc += Psum[((q * 4 + 2) * 64 + eb) * PJ + ej];
            go += Psum[((q * 4 + 3) * 64 + eb) * PJ + ej];
        }
        c_reg = sigf(gf) * c_reg + sigf(gi) * tanhx(gc);
        float hval = sigf(go) * tanhx(c_reg);
        g_hs_buf[(size_t)(s + 1) * HSLOT + (e0 + ej) * 64 + eb] = hval;
        {   // bf16 hi/lo planes for the output GEMM
            __nv_bfloat16 hb16 = __float2bfloat16(hval);
            size_t ai = ((size_t)(s * BATCH + eb)) * HIDDEN + e0 + ej;
            A_hs_hi[ai] = hb16;
            A_hs_lo[ai] = __float2bfloat16(hval - __bfloat162float(hb16));
        }

        __threadfence();
        __syncthreads();
        if (tid == 0) {
            unsigned a = atomicAdd(&g_arrive, 1u);
            if (a == (unsigned)(gridDim.x - 1)) {
                atomicExch(&g_arrive, 0u);
                __threadfence();
                g_epoch = (unsigned)(s + 1);
            } else {
                while (g_epoch < (unsigned)(s + 1)) __nanosleep(64);
            }
            __threadfence();
        }
        __syncthreads();
    }

    g_c[eb * HIDDEN + e0 + ej] = c_reg;
}

// ---------------- tail: ht, ct ---------------------------------------------
__global__ void k_tail(float* out) {
    int i = blockIdx.x * blockDim.x + threadIdx.x;
    size_t base = (size_t)ROWS * VOCAB;
    if (i < BATCH * HIDDEN) {
        int b = i >> 9, e = i & 511;
        out[base + i] = g_hs_buf[(size_t)SEQ * HSLOT + e * 64 + b];
    } else if (i < 2 * BATCH * HIDDEN) {
        out[base + i] = g_c[i - BATCH * HIDDEN];
    }
}

// ---------------- launch ----------------------------------------------------
extern "C" void kernel_launch(void* const* d_in, const int* in_sizes, int n_in,
                              void* d_out, int out_size) {
    const int*   input_ = (const int*)  d_in[0];
    const float* emb    = (const float*)d_in[1];
    const float* wxi    = (const float*)d_in[2];
    const float* whi    = (const float*)d_in[3];
    const float* bi     = (const float*)d_in[4];
    const float* wxf    = (const float*)d_in[5];
    const float* whf    = (const float*)d_in[6];
    const float* bf     = (const float*)d_in[7];
    const float* wxc    = (const float*)d_in[8];
    const float* whc    = (const float*)d_in[9];
    const float* bc     = (const float*)d_in[10];
    const float* wxo    = (const float*)d_in[11];
    const float* who    = (const float*)d_in[12];
    const float* bo     = (const float*)d_in[13];
    const float* wy     = (const float*)d_in[14];
    const float* by     = (const float*)d_in[15];
    float* out = (float*)d_out;

    cudaFuncSetAttribute(k_lstm,   cudaFuncAttributeMaxDynamicSharedMemorySize, SM_TOT_L);
    cudaFuncSetAttribute(k_gemm_x, cudaFuncAttributeMaxDynamicSharedMemorySize, GB_TOT);
    cudaFuncSetAttribute(k_gemm_o, cudaFuncAttributeMaxDynamicSharedMemorySize, GB_TOT);

    k_init<<<NCTA, NTHR>>>();

    k_cvtA_emb<<<(ROWS * EMBED) / 256, 256>>>(input_, emb);
    k_cvtBx<<<dim3(8, 512), 256>>>(wxi, wxf, wxc, wxo, bi, bf, bc, bo);
    k_cvtBy<<<dim3(40, 512), 256>>>(wy);

    k_gemm_x<<<dim3(8, 128), 256, GB_TOT>>>();

    k_lstm<<<NCTA, NTHR, SM_TOT_L>>>(whi, whf, whc, who);

    k_gemm_o<<<dim3(40, 128), 256, GB_TOT>>>(by, out);

    if ((long long)out_size >= (long long)ROWS * VOCAB + 2LL * BATCH * HIDDEN)
        k_tail<<<(2 * BATCH * HIDDEN + 255) / 256, 256>>>(out);
}